// round 2
// baseline (speedup 1.0000x reference)
#include <cuda_runtime.h>
#include <cstdint>

// Problem constants
#define BB 8
#define NN 4096
#define EE 2048
#define CC 128

// GEMM tiling
#define BM 128
#define BN 128
#define BK 32
#define LDT 132   // smem tile row stride in words ([BK][LDT])

// Scratch (device globals: no allocations allowed)
__device__ float g_e [BB * EE * CC];   // normalized edge features (pre-fc)
__device__ float g_ef[BB * EE * CC];   // edge features after fc
__device__ float g_de[BB * EE];        // edge degrees

__device__ __forceinline__ unsigned f2tf(float f) {
    unsigned r;
    asm("cvt.rna.tf32.f32 %0, %1;" : "=r"(r) : "f"(f));
    return r;
}

__device__ __forceinline__ void mma8(float* c, const unsigned* a, const unsigned* b) {
    asm volatile(
        "mma.sync.aligned.m16n8k8.row.col.f32.tf32.tf32.f32 "
        "{%0,%1,%2,%3}, {%4,%5,%6,%7}, {%8,%9}, {%0,%1,%2,%3};"
        : "+f"(c[0]), "+f"(c[1]), "+f"(c[2]), "+f"(c[3])
        : "r"(a[0]), "r"(a[1]), "r"(a[2]), "r"(a[3]),
          "r"(b[0]), "r"(b[1]));
}

// Swizzled A-tile index: element (k, m) -> As[k*LDT + (m ^ (k & 0x1C))]
// Keeps both transposed staging stores and fragment loads (near-)conflict-free.
__device__ __forceinline__ int aidx(int k, int m) {
    return k * LDT + (m ^ (k & 0x1C));
}

// MODE 0: v2e   e_norm[b,e,c] = (H^T x)/de         grid (E/BM, B), K = N
// MODE 1: fc    e_fc[b,e,c]   = mask(de)*(e_norm W + bias)  grid (E/BM, B), K = C
// MODE 2: e2v   v[b,n,c]      = (H e_fc)/dv        grid (N/BM, B), K = E
template <int MODE>
__global__ __launch_bounds__(256)
void gemm_kernel(const float* __restrict__ x, const float* __restrict__ H,
                 const float* __restrict__ W, const float* __restrict__ bias,
                 float* __restrict__ out)
{
    constexpr int KTOT   = (MODE == 0) ? NN : (MODE == 1 ? CC : EE);
    constexpr int NCHUNK = KTOT / BK;

    __shared__ unsigned As[BK * LDT];
    __shared__ unsigned Bs[BK * LDT];
    __shared__ float    red_s[2 * BM];
    __shared__ float    deg_s[BM];

    const int t    = threadIdx.x;
    const int lane = t & 31;
    const int wid  = t >> 5;
    const int tile = blockIdx.x;
    const int b    = blockIdx.y;
    const int m0g  = tile * BM;

    const int wm  = wid >> 1;   // 4 warp-rows of 32
    const int wn  = wid & 1;    // 2 warp-cols of 64
    const int gid = lane >> 2;
    const int tig = lane & 3;

    const float* __restrict__ Hb = H + (size_t)b * NN * EE;

    float acc[2][8][4];
#pragma unroll
    for (int i = 0; i < 2; i++)
#pragma unroll
        for (int j = 0; j < 8; j++)
#pragma unroll
            for (int r = 0; r < 4; r++) acc[i][j][r] = 0.f;

    float degacc[16];
#pragma unroll
    for (int i = 0; i < 16; i++) degacc[i] = 0.f;

    for (int kc = 0; kc < NCHUNK; kc++) {
        const int kg0 = kc * BK;
        __syncthreads();

        // ---- stage A (and fold degree accumulation into staging) ----
        if (MODE == 0) {
            // As[k][m] = H[b][kg0+k][m0g+m]  (transposed staging of H)
            const int ml = t & 127;
#pragma unroll
            for (int i = 0; i < 16; i++) {
                const int kl = (t >> 7) + 2 * i;
                const float v = Hb[(size_t)(kg0 + kl) * EE + m0g + ml];
                As[aidx(kl, ml)] = __float_as_uint(v);   // 0/1: exact in tf32
                degacc[0] += v;                           // de partial (m fixed per thread)
            }
        } else if (MODE == 1) {
            // As[k][m] = tf32(g_e[b][m0g+m][kg0+k])
            const int kl = t & 31;
#pragma unroll
            for (int i = 0; i < 16; i++) {
                const int ml = wid + 8 * i;
                const float v = g_e[((size_t)b * EE + m0g + ml) * CC + kg0 + kl];
                As[aidx(kl, ml)] = f2tf(v);
            }
        } else {
            // As[k][m] = H[b][m0g+m][kg0+k]  (natural K-major)
            const int kl = t & 31;   // = lane
#pragma unroll
            for (int i = 0; i < 16; i++) {
                const int ml = wid + 8 * i;
                const float v = Hb[(size_t)(m0g + ml) * EE + kg0 + kl];
                As[aidx(kl, ml)] = __float_as_uint(v);
                degacc[i] += v;      // dv partial (row ml = wid+8i, lanes hold e-slices)
            }
        }

        // ---- stage B ----
        {
            const int nl = t & 127;
#pragma unroll
            for (int i = 0; i < 16; i++) {
                const int kl = (t >> 7) + 2 * i;
                float v;
                if (MODE == 0)
                    v = x[((size_t)b * NN + kg0 + kl) * CC + nl];
                else if (MODE == 1)
                    v = W[(size_t)(kg0 + kl) * CC + nl];
                else
                    v = g_ef[((size_t)b * EE + kg0 + kl) * CC + nl];
                Bs[kl * LDT + nl] = f2tf(v);
            }
        }
        __syncthreads();

        // ---- compute ----
#pragma unroll
        for (int ks = 0; ks < 4; ks++) {
            const int k0 = ks * 8;
            unsigned a[2][4], bf[8][2];
#pragma unroll
            for (int mt = 0; mt < 2; mt++) {
                const int mrow = wm * 32 + mt * 16 + gid;
                a[mt][0] = As[aidx(k0 + tig,     mrow)];
                a[mt][1] = As[aidx(k0 + tig,     mrow + 8)];
                a[mt][2] = As[aidx(k0 + 4 + tig, mrow)];
                a[mt][3] = As[aidx(k0 + 4 + tig, mrow + 8)];
            }
#pragma unroll
            for (int j = 0; j < 8; j++) {
                const int ncol = wn * 64 + j * 8 + gid;
                bf[j][0] = Bs[(k0 + tig) * LDT + ncol];
                bf[j][1] = Bs[(k0 + 4 + tig) * LDT + ncol];
            }
#pragma unroll
            for (int mt = 0; mt < 2; mt++)
#pragma unroll
                for (int j = 0; j < 8; j++)
                    mma8(acc[mt][j], a[mt], bf[j]);
        }
    }

    // ---- finalize per-row degrees in deg_s ----
    if (MODE == 0) {
        red_s[t] = degacc[0];
        __syncthreads();
        if (t < BM) {
            const float d = red_s[t] + red_s[t + 128];
            deg_s[t] = d;
            g_de[(size_t)b * EE + m0g + t] = d;
        }
        __syncthreads();
    } else if (MODE == 1) {
        __syncthreads();
        if (t < BM) deg_s[t] = g_de[(size_t)b * EE + m0g + t];
        __syncthreads();
    } else {
#pragma unroll
        for (int i = 0; i < 16; i++) {
            float v = degacc[i];
#pragma unroll
            for (int o = 16; o; o >>= 1) v += __shfl_xor_sync(0xffffffffu, v, o);
            if (lane == 0) deg_s[wid + 8 * i] = v;
        }
        __syncthreads();
    }

    // ---- epilogue: normalize (or +bias/mask) and store ----
#pragma unroll
    for (int mt = 0; mt < 2; mt++) {
        const int r0 = wm * 32 + mt * 16 + gid;
#pragma unroll
        for (int rh = 0; rh < 2; rh++) {
            const int row = r0 + rh * 8;
            const float d   = deg_s[row];
            const float inv = (d > 0.f) ? 1.f / d : 0.f;
#pragma unroll
            for (int j = 0; j < 8; j++) {
                const int col = wn * 64 + j * 8 + tig * 2;
                const float v0 = acc[mt][j][rh * 2 + 0];
                const float v1 = acc[mt][j][rh * 2 + 1];
                if (MODE == 0) {
                    g_e[((size_t)b * EE + m0g + row) * CC + col]     = v0 * inv;
                    g_e[((size_t)b * EE + m0g + row) * CC + col + 1] = v1 * inv;
                } else if (MODE == 1) {
                    const float msk = (d > 0.f) ? 1.f : 0.f;
                    g_ef[((size_t)b * EE + m0g + row) * CC + col]     = msk * (v0 + bias[col]);
                    g_ef[((size_t)b * EE + m0g + row) * CC + col + 1] = msk * (v1 + bias[col + 1]);
                } else {
                    out[((size_t)b * NN + m0g + row) * CC + col]     = v0 * inv;
                    out[((size_t)b * NN + m0g + row) * CC + col + 1] = v1 * inv;
                }
            }
        }
    }
}

extern "C" void kernel_launch(void* const* d_in, const int* in_sizes, int n_in,
                              void* d_out, int out_size)
{
    const float* x    = (const float*)d_in[0];
    const float* H    = (const float*)d_in[1];
    const float* W    = (const float*)d_in[2];
    const float* bias = (const float*)d_in[3];
    float* out = (float*)d_out;

    gemm_kernel<0><<<dim3(EE / BM, BB), 256>>>(x, H, W, bias, out);  // v2e + de
    gemm_kernel<1><<<dim3(EE / BM, BB), 256>>>(x, H, W, bias, out);  // fc at edge level
    gemm_kernel<2><<<dim3(NN / BM, BB), 256>>>(x, H, W, bias, out);  // e2v + dv
}

// round 3
// speedup vs baseline: 2.3458x; 2.3458x over previous
#include <cuda_runtime.h>
#include <cstdint>

// Problem constants
#define BB 8
#define NN 4096
#define EE 2048
#define CC 128

// GEMM tiling
#define BM 128
#define BN 128
#define BK 32
#define LDA 136   // As row stride (words) for [k][m] layout (modes 0,1): bank = 8*tig+gid, conflict-free
#define LDB 136   // Bs row stride (words): conflict-free fragment loads
#define LDK 36    // As row stride (words) for [m][k] layout (mode 2): bank = 4*gid+tig, conflict-free

#define ASZ01 (BK * LDA)    // 4352 words
#define ASZ2  (BM * LDK)    // 4608 words
#define BSZ   (BK * LDB)    // 4352 words

// Scratch (device globals; no allocations allowed)
__device__ float g_e2 [2 * BB * EE * CC];  // split-K partial edge features (unnormalized)
__device__ float g_de2[2 * BB * EE];       // split-K partial edge degrees
__device__ float g_ef [BB * EE * CC];      // edge features after fc

__device__ __forceinline__ unsigned f2tf(float f) {
    unsigned r;
    asm("cvt.rna.tf32.f32 %0, %1;" : "=r"(r) : "f"(f));
    return r;
}

__device__ __forceinline__ void mma8(float* c, const unsigned* a, const unsigned* b) {
    asm volatile(
        "mma.sync.aligned.m16n8k8.row.col.f32.tf32.tf32.f32 "
        "{%0,%1,%2,%3}, {%4,%5,%6,%7}, {%8,%9}, {%0,%1,%2,%3};"
        : "+f"(c[0]), "+f"(c[1]), "+f"(c[2]), "+f"(c[3])
        : "r"(a[0]), "r"(a[1]), "r"(a[2]), "r"(a[3]),
          "r"(b[0]), "r"(b[1]));
}

__device__ __forceinline__ void cpa16(uint32_t dst, const float* src) {
    asm volatile("cp.async.cg.shared.global [%0], [%1], 16;\n" :: "r"(dst), "l"(src));
}
__device__ __forceinline__ void cp_commit() {
    asm volatile("cp.async.commit_group;\n");
}

// MODE 0: v2e partial  g_e2[s] = (H^T x) over K-split s; g_de2[s] = partial edge degrees
//         grid (E/BM, B, 2), K = N/2 per CTA
// MODE 1: fc           g_ef = mask(de) * ((sum_s g_e2[s]) W / de + bias)
//         grid (E/BM, B), K = C
// MODE 2: e2v          out = (H g_ef) / dv     grid (N/BM, B), K = E
template <int MODE>
__global__ void __launch_bounds__(256, 2)
gemm_kernel(const float* __restrict__ x, const float* __restrict__ H,
            const float* __restrict__ W, const float* __restrict__ bias,
            float* __restrict__ out)
{
    constexpr int SPLIT  = (MODE == 0) ? 2 : 1;
    constexpr int KTOT   = (MODE == 0) ? NN : (MODE == 1 ? CC : EE);
    constexpr int CHUNKS = KTOT / BK / SPLIT;
    constexpr int ASZ    = (MODE == 2) ? ASZ2 : ASZ01;

    extern __shared__ float sm[];
    __shared__ float deg_s[BM];

    const int t    = threadIdx.x;
    const int lane = t & 31;
    const int wid  = t >> 5;
    const int b    = blockIdx.y;
    const int m0g  = blockIdx.x * BM;
    const int split = (MODE == 0) ? blockIdx.z : 0;
    const int kbase = split * CHUNKS * BK;

    const int wm  = wid >> 1;   // 4 warp-rows of 32
    const int wn  = wid & 1;    // 2 warp-cols of 64
    const int gid = lane >> 2;
    const int tig = lane & 3;

    const float* __restrict__ Hb = H + (size_t)b * NN * EE;
    const uint32_t smbase = (uint32_t)__cvta_generic_to_shared(sm);

    float acc[2][8][4];
#pragma unroll
    for (int i = 0; i < 2; i++)
#pragma unroll
        for (int j = 0; j < 8; j++)
#pragma unroll
            for (int r = 0; r < 4; r++) acc[i][j][r] = 0.f;

    float degacc[2][2] = {{0.f, 0.f}, {0.f, 0.f}};

    // ---------------- staging ----------------
    auto stage = [&](int kc, int buf) {
        const int kg0 = kbase + kc * BK;
        const uint32_t aB = smbase + (uint32_t)(buf * ASZ) * 4u;
        const uint32_t bB = smbase + (uint32_t)(2 * ASZ + buf * BSZ) * 4u;
        if (MODE == 0) {
            // As[k][m] = H[b][kg0+k][m0g+m]  (transposed tile of H)
#pragma unroll
            for (int i = 0; i < 4; i++) {
                const int idx = t + 256 * i;       // 0..1023 16B groups
                const int k = idx >> 5, m = (idx & 31) * 4;
                cpa16(aB + (uint32_t)(k * LDA + m) * 4u,
                      Hb + (size_t)(kg0 + k) * EE + m0g + m);
            }
        } else if (MODE == 2) {
            // As[m][k] = H[b][m0g+m][kg0+k]  (natural K-major)
#pragma unroll
            for (int i = 0; i < 4; i++) {
                const int idx = t + 256 * i;
                const int m = idx >> 3, kk = (idx & 7) * 4;
                cpa16(aB + (uint32_t)(m * LDK + kk) * 4u,
                      Hb + (size_t)(m0g + m) * EE + kg0 + kk);
            }
        } else {
            // MODE 1: As[k][m] = tf32(sum_s g_e2[s][b][m0g+m][kg0+k])  (register staging)
            float* Asf = sm + buf * ASZ;
#pragma unroll
            for (int i = 0; i < 16; i++) {
                const int idx = t + 256 * i;       // 0..4095 elements
                const int k = idx & 31, m = idx >> 5;
                const size_t off = ((size_t)b * EE + m0g + m) * CC + kg0 + k;
                const float v = g_e2[off] + g_e2[(size_t)BB * EE * CC + off];
                Asf[k * LDA + m] = __uint_as_float(f2tf(v));
            }
        }
        // B tile: Bs[k][n]
        const float* Bsrc = (MODE == 0) ? x    + ((size_t)b * NN + kg0) * CC
                          : (MODE == 1) ? W    + (size_t)kg0 * CC
                          :               g_ef + ((size_t)b * EE + kg0) * CC;
#pragma unroll
        for (int i = 0; i < 4; i++) {
            const int idx = t + 256 * i;
            const int k = idx >> 5, n = (idx & 31) * 4;
            cpa16(bB + (uint32_t)(k * LDB + n) * 4u, Bsrc + (size_t)k * CC + n);
        }
    };

    // ---------------- compute ----------------
    auto compute = [&](int buf) {
        const float* As = sm + buf * ASZ;
        const float* Bs = sm + 2 * ASZ + buf * BSZ;
#pragma unroll
        for (int ks = 0; ks < 4; ks++) {
            const int k0 = ks * 8;
            unsigned a[2][4], bf[8][2];
#pragma unroll
            for (int mt = 0; mt < 2; mt++) {
                const int mrow = wm * 32 + mt * 16 + gid;
                if (MODE == 2) {
                    a[mt][0] = __float_as_uint(As[(mrow    ) * LDK + k0 + tig]);
                    a[mt][1] = __float_as_uint(As[(mrow + 8) * LDK + k0 + tig]);
                    a[mt][2] = __float_as_uint(As[(mrow    ) * LDK + k0 + 4 + tig]);
                    a[mt][3] = __float_as_uint(As[(mrow + 8) * LDK + k0 + 4 + tig]);
                } else {
                    a[mt][0] = __float_as_uint(As[(k0 + tig    ) * LDA + mrow]);
                    a[mt][1] = __float_as_uint(As[(k0 + tig    ) * LDA + mrow + 8]);
                    a[mt][2] = __float_as_uint(As[(k0 + 4 + tig) * LDA + mrow]);
                    a[mt][3] = __float_as_uint(As[(k0 + 4 + tig) * LDA + mrow + 8]);
                }
            }
            // Degrees fold out of the already-loaded binary-H fragments (wn==0 copy only)
            if (MODE != 1 && wn == 0) {
#pragma unroll
                for (int mt = 0; mt < 2; mt++) {
                    degacc[mt][0] += __uint_as_float(a[mt][0]) + __uint_as_float(a[mt][2]);
                    degacc[mt][1] += __uint_as_float(a[mt][1]) + __uint_as_float(a[mt][3]);
                }
            }
#pragma unroll
            for (int j = 0; j < 8; j++) {
                const int ncol = wn * 64 + j * 8 + gid;
                bf[j][0] = f2tf(Bs[(k0 + tig    ) * LDB + ncol]);
                bf[j][1] = f2tf(Bs[(k0 + 4 + tig) * LDB + ncol]);
            }
#pragma unroll
            for (int mt = 0; mt < 2; mt++)
#pragma unroll
                for (int j = 0; j < 8; j++)
                    mma8(acc[mt][j], a[mt], bf[j]);
        }
    };

    // ---------------- pipelined mainloop ----------------
    stage(0, 0);
    cp_commit();
    for (int kc = 0; kc < CHUNKS; kc++) {
        if (kc + 1 < CHUNKS) {
            stage(kc + 1, (kc + 1) & 1);
            cp_commit();
            asm volatile("cp.async.wait_group 1;\n");
        } else {
            asm volatile("cp.async.wait_group 0;\n");
        }
        __syncthreads();
        compute(kc & 1);
        __syncthreads();
    }

    // ---------------- degrees ----------------
    if (MODE == 0) {
        // write partial degrees for this K-split
#pragma unroll
        for (int mt = 0; mt < 2; mt++)
#pragma unroll
            for (int rh = 0; rh < 2; rh++) {
                float v = degacc[mt][rh];
                v += __shfl_xor_sync(0xffffffffu, v, 1);
                v += __shfl_xor_sync(0xffffffffu, v, 2);
                if (wn == 0 && tig == 0) {
                    const int row = wm * 32 + mt * 16 + rh * 8 + gid;
                    g_de2[(size_t)split * BB * EE + (size_t)b * EE + m0g + row] = v;
                }
            }
    } else if (MODE == 1) {
        if (t < BM) {
            const size_t o = (size_t)b * EE + m0g + t;
            deg_s[t] = g_de2[o] + g_de2[(size_t)BB * EE + o];
        }
        __syncthreads();
    } else {
#pragma unroll
        for (int mt = 0; mt < 2; mt++)
#pragma unroll
            for (int rh = 0; rh < 2; rh++) {
                float v = degacc[mt][rh];
                v += __shfl_xor_sync(0xffffffffu, v, 1);
                v += __shfl_xor_sync(0xffffffffu, v, 2);
                if (wn == 0 && tig == 0)
                    deg_s[wm * 32 + mt * 16 + rh * 8 + gid] = v;
            }
        __syncthreads();
    }

    // ---------------- epilogue ----------------
#pragma unroll
    for (int mt = 0; mt < 2; mt++) {
#pragma unroll
        for (int rh = 0; rh < 2; rh++) {
            const int row = wm * 32 + mt * 16 + rh * 8 + gid;
            float inv = 1.f, msk = 1.f;
            if (MODE != 0) {
                const float d = deg_s[row];
                inv = (d > 0.f) ? 1.f / d : 0.f;
                msk = (d > 0.f) ? 1.f : 0.f;
            }
#pragma unroll
            for (int j = 0; j < 8; j++) {
                const int col = wn * 64 + j * 8 + tig * 2;
                const float v0 = acc[mt][j][rh * 2 + 0];
                const float v1 = acc[mt][j][rh * 2 + 1];
                if (MODE == 0) {
                    float2 p = make_float2(v0, v1);
                    *(float2*)&g_e2[(size_t)split * BB * EE * CC +
                                    ((size_t)b * EE + m0g + row) * CC + col] = p;
                } else if (MODE == 1) {
                    float2 p = make_float2(msk * (v0 * inv + bias[col]),
                                           msk * (v1 * inv + bias[col + 1]));
                    *(float2*)&g_ef[((size_t)b * EE + m0g + row) * CC + col] = p;
                } else {
                    float2 p = make_float2(v0 * inv, v1 * inv);
                    *(float2*)&out[((size_t)b * NN + m0g + row) * CC + col] = p;
                }
            }
        }
    }
}

extern "C" void kernel_launch(void* const* d_in, const int* in_sizes, int n_in,
                              void* d_out, int out_size)
{
    const float* x    = (const float*)d_in[0];
    const float* H    = (const float*)d_in[1];
    const float* W    = (const float*)d_in[2];
    const float* bias = (const float*)d_in[3];
    float* out = (float*)d_out;

    const int sm01 = (2 * ASZ01 + 2 * BSZ) * 4;   // 69632 B
    const int sm2  = (2 * ASZ2  + 2 * BSZ) * 4;   // 71680 B
    cudaFuncSetAttribute(gemm_kernel<0>, cudaFuncAttributeMaxDynamicSharedMemorySize, sm01);
    cudaFuncSetAttribute(gemm_kernel<1>, cudaFuncAttributeMaxDynamicSharedMemorySize, sm01);
    cudaFuncSetAttribute(gemm_kernel<2>, cudaFuncAttributeMaxDynamicSharedMemorySize, sm2);

    gemm_kernel<0><<<dim3(EE / BM, BB, 2), 256, sm01>>>(x, H, W, bias, out);  // v2e split-K partials
    gemm_kernel<1><<<dim3(EE / BM, BB, 1), 256, sm01>>>(x, H, W, bias, out);  // combine + normalize + fc
    gemm_kernel<2><<<dim3(NN / BM, BB, 1), 256, sm2 >>>(x, H, W, bias, out);  // e2v + dv
}

// round 4
// speedup vs baseline: 2.3479x; 1.0009x over previous
#include <cuda_runtime.h>
#include <cstdint>

// Problem constants
#define BB 8
#define NN 4096
#define EE 2048
#define CC 128

// GEMM tiling
#define BM 128
#define BN 128
#define BK 32
#define LDA 136   // As row stride (words) for [k][m] layout (modes 0,1): bank = 8*tig+gid, conflict-free
#define LDB 136   // Bs row stride (words): conflict-free fragment loads
#define LDK 36    // As row stride (words) for [m][k] layout (mode 2): bank = 4*gid+tig, conflict-free

#define ASZ01 (BK * LDA)    // 4352 words
#define ASZ2  (BM * LDK)    // 4608 words
#define BSZ   (BK * LDB)    // 4352 words

// Scratch (device globals; no allocations allowed)
__device__ float g_e2 [2 * BB * EE * CC];  // split-K partial edge features (unnormalized)
__device__ float g_de2[2 * BB * EE];       // split-K partial edge degrees
__device__ float g_ef [BB * EE * CC];      // edge features after fc

__device__ __forceinline__ unsigned f2tf(float f) {
    unsigned r;
    asm("cvt.rna.tf32.f32 %0, %1;" : "=r"(r) : "f"(f));
    return r;
}

__device__ __forceinline__ void mma8(float* c, const unsigned* a, const unsigned* b) {
    asm volatile(
        "mma.sync.aligned.m16n8k8.row.col.f32.tf32.tf32.f32 "
        "{%0,%1,%2,%3}, {%4,%5,%6,%7}, {%8,%9}, {%0,%1,%2,%3};"
        : "+f"(c[0]), "+f"(c[1]), "+f"(c[2]), "+f"(c[3])
        : "r"(a[0]), "r"(a[1]), "r"(a[2]), "r"(a[3]),
          "r"(b[0]), "r"(b[1]));
}

__device__ __forceinline__ void cpa16(uint32_t dst, const float* src) {
    asm volatile("cp.async.cg.shared.global [%0], [%1], 16;\n" :: "r"(dst), "l"(src));
}
__device__ __forceinline__ void cp_commit() {
    asm volatile("cp.async.commit_group;\n");
}

// MODE 0: v2e partial  g_e2[s] = (H^T x) over K-split s; g_de2[s] = partial edge degrees
//         grid (E/BM, B, 2), K = N/2 per CTA
// MODE 1: fc           g_ef = mask(de) * ((sum_s g_e2[s]) W / de + bias)
//         grid (E/BM, B), K = C
// MODE 2: e2v          out = (H g_ef) / dv     grid (N/BM, B), K = E
template <int MODE>
__global__ void __launch_bounds__(256, 2)
gemm_kernel(const float* __restrict__ x, const float* __restrict__ H,
            const float* __restrict__ W, const float* __restrict__ bias,
            float* __restrict__ out)
{
    constexpr int SPLIT  = (MODE == 0) ? 2 : 1;
    constexpr int KTOT   = (MODE == 0) ? NN : (MODE == 1 ? CC : EE);
    constexpr int CHUNKS = KTOT / BK / SPLIT;
    constexpr int ASZ    = (MODE == 2) ? ASZ2 : ASZ01;

    extern __shared__ float sm[];
    __shared__ float deg_s[BM];

    const int t    = threadIdx.x;
    const int lane = t & 31;
    const int wid  = t >> 5;
    const int b    = blockIdx.y;
    const int m0g  = blockIdx.x * BM;
    const int split = (MODE == 0) ? blockIdx.z : 0;
    const int kbase = split * CHUNKS * BK;

    const int wm  = wid >> 1;   // 4 warp-rows of 32
    const int wn  = wid & 1;    // 2 warp-cols of 64
    const int gid = lane >> 2;
    const int tig = lane & 3;

    const float* __restrict__ Hb = H + (size_t)b * NN * EE;
    const uint32_t smbase = (uint32_t)__cvta_generic_to_shared(sm);

    float acc[2][8][4];
#pragma unroll
    for (int i = 0; i < 2; i++)
#pragma unroll
        for (int j = 0; j < 8; j++)
#pragma unroll
            for (int r = 0; r < 4; r++) acc[i][j][r] = 0.f;

    float degacc[2][2] = {{0.f, 0.f}, {0.f, 0.f}};

    // ---------------- staging ----------------
    auto stage = [&](int kc, int buf) {
        const int kg0 = kbase + kc * BK;
        const uint32_t aB = smbase + (uint32_t)(buf * ASZ) * 4u;
        const uint32_t bB = smbase + (uint32_t)(2 * ASZ + buf * BSZ) * 4u;
        if (MODE == 0) {
            // As[k][m] = H[b][kg0+k][m0g+m]  (transposed tile of H)
#pragma unroll
            for (int i = 0; i < 4; i++) {
                const int idx = t + 256 * i;       // 0..1023 16B groups
                const int k = idx >> 5, m = (idx & 31) * 4;
                cpa16(aB + (uint32_t)(k * LDA + m) * 4u,
                      Hb + (size_t)(kg0 + k) * EE + m0g + m);
            }
        } else if (MODE == 2) {
            // As[m][k] = H[b][m0g+m][kg0+k]  (natural K-major)
#pragma unroll
            for (int i = 0; i < 4; i++) {
                const int idx = t + 256 * i;
                const int m = idx >> 3, kk = (idx & 7) * 4;
                cpa16(aB + (uint32_t)(m * LDK + kk) * 4u,
                      Hb + (size_t)(m0g + m) * EE + kg0 + kk);
            }
        } else {
            // MODE 1: As[k][m] = tf32(sum_s g_e2[s][b][m0g+m][kg0+k])  (register staging)
            float* Asf = sm + buf * ASZ;
#pragma unroll
            for (int i = 0; i < 16; i++) {
                const int idx = t + 256 * i;       // 0..4095 elements
                const int k = idx & 31, m = idx >> 5;
                const size_t off = ((size_t)b * EE + m0g + m) * CC + kg0 + k;
                const float v = g_e2[off] + g_e2[(size_t)BB * EE * CC + off];
                Asf[k * LDA + m] = __uint_as_float(f2tf(v));
            }
        }
        // B tile: Bs[k][n]
        const float* Bsrc = (MODE == 0) ? x    + ((size_t)b * NN + kg0) * CC
                          : (MODE == 1) ? W    + (size_t)kg0 * CC
                          :               g_ef + ((size_t)b * EE + kg0) * CC;
#pragma unroll
        for (int i = 0; i < 4; i++) {
            const int idx = t + 256 * i;
            const int k = idx >> 5, n = (idx & 31) * 4;
            cpa16(bB + (uint32_t)(k * LDB + n) * 4u, Bsrc + (size_t)k * CC + n);
        }
    };

    // ---------------- compute ----------------
    auto compute = [&](int buf) {
        const float* As = sm + buf * ASZ;
        const float* Bs = sm + 2 * ASZ + buf * BSZ;
#pragma unroll
        for (int ks = 0; ks < 4; ks++) {
            const int k0 = ks * 8;
            unsigned a[2][4], bf[8][2];
#pragma unroll
            for (int mt = 0; mt < 2; mt++) {
                const int mrow = wm * 32 + mt * 16 + gid;
                if (MODE == 2) {
                    a[mt][0] = __float_as_uint(As[(mrow    ) * LDK + k0 + tig]);
                    a[mt][1] = __float_as_uint(As[(mrow + 8) * LDK + k0 + tig]);
                    a[mt][2] = __float_as_uint(As[(mrow    ) * LDK + k0 + 4 + tig]);
                    a[mt][3] = __float_as_uint(As[(mrow + 8) * LDK + k0 + 4 + tig]);
                } else {
                    a[mt][0] = __float_as_uint(As[(k0 + tig    ) * LDA + mrow]);
                    a[mt][1] = __float_as_uint(As[(k0 + tig    ) * LDA + mrow + 8]);
                    a[mt][2] = __float_as_uint(As[(k0 + 4 + tig) * LDA + mrow]);
                    a[mt][3] = __float_as_uint(As[(k0 + 4 + tig) * LDA + mrow + 8]);
                }
            }
            // Degrees fold out of the already-loaded binary-H fragments (wn==0 copy only)
            if (MODE != 1 && wn == 0) {
#pragma unroll
                for (int mt = 0; mt < 2; mt++) {
                    degacc[mt][0] += __uint_as_float(a[mt][0]) + __uint_as_float(a[mt][2]);
                    degacc[mt][1] += __uint_as_float(a[mt][1]) + __uint_as_float(a[mt][3]);
                }
            }
#pragma unroll
            for (int j = 0; j < 8; j++) {
                const int ncol = wn * 64 + j * 8 + gid;
                bf[j][0] = f2tf(Bs[(k0 + tig    ) * LDB + ncol]);
                bf[j][1] = f2tf(Bs[(k0 + 4 + tig) * LDB + ncol]);
            }
#pragma unroll
            for (int mt = 0; mt < 2; mt++)
#pragma unroll
                for (int j = 0; j < 8; j++)
                    mma8(acc[mt][j], a[mt], bf[j]);
        }
    };

    // ---------------- pipelined mainloop ----------------
    stage(0, 0);
    cp_commit();
    for (int kc = 0; kc < CHUNKS; kc++) {
        if (kc + 1 < CHUNKS) {
            stage(kc + 1, (kc + 1) & 1);
            cp_commit();
            asm volatile("cp.async.wait_group 1;\n");
        } else {
            asm volatile("cp.async.wait_group 0;\n");
        }
        __syncthreads();
        compute(kc & 1);
        __syncthreads();
    }

    // ---------------- degrees ----------------
    if (MODE == 0) {
        // write partial degrees for this K-split
#pragma unroll
        for (int mt = 0; mt < 2; mt++)
#pragma unroll
            for (int rh = 0; rh < 2; rh++) {
                float v = degacc[mt][rh];
                v += __shfl_xor_sync(0xffffffffu, v, 1);
                v += __shfl_xor_sync(0xffffffffu, v, 2);
                if (wn == 0 && tig == 0) {
                    const int row = wm * 32 + mt * 16 + rh * 8 + gid;
                    g_de2[(size_t)split * BB * EE + (size_t)b * EE + m0g + row] = v;
                }
            }
    } else if (MODE == 1) {
        if (t < BM) {
            const size_t o = (size_t)b * EE + m0g + t;
            deg_s[t] = g_de2[o] + g_de2[(size_t)BB * EE + o];
        }
        __syncthreads();
    } else {
#pragma unroll
        for (int mt = 0; mt < 2; mt++)
#pragma unroll
            for (int rh = 0; rh < 2; rh++) {
                float v = degacc[mt][rh];
                v += __shfl_xor_sync(0xffffffffu, v, 1);
                v += __shfl_xor_sync(0xffffffffu, v, 2);
                if (wn == 0 && tig == 0)
                    deg_s[wm * 32 + mt * 16 + rh * 8 + gid] = v;
            }
        __syncthreads();
    }

    // ---------------- epilogue ----------------
#pragma unroll
    for (int mt = 0; mt < 2; mt++) {
#pragma unroll
        for (int rh = 0; rh < 2; rh++) {
            const int row = wm * 32 + mt * 16 + rh * 8 + gid;
            float inv = 1.f, msk = 1.f;
            if (MODE != 0) {
                const float d = deg_s[row];
                inv = (d > 0.f) ? 1.f / d : 0.f;
                msk = (d > 0.f) ? 1.f : 0.f;
            }
#pragma unroll
            for (int j = 0; j < 8; j++) {
                const int col = wn * 64 + j * 8 + tig * 2;
                const float v0 = acc[mt][j][rh * 2 + 0];
                const float v1 = acc[mt][j][rh * 2 + 1];
                if (MODE == 0) {
                    float2 p = make_float2(v0, v1);
                    *(float2*)&g_e2[(size_t)split * BB * EE * CC +
                                    ((size_t)b * EE + m0g + row) * CC + col] = p;
                } else if (MODE == 1) {
                    float2 p = make_float2(msk * (v0 * inv + bias[col]),
                                           msk * (v1 * inv + bias[col + 1]));
                    *(float2*)&g_ef[((size_t)b * EE + m0g + row) * CC + col] = p;
                } else {
                    float2 p = make_float2(v0 * inv, v1 * inv);
                    *(float2*)&out[((size_t)b * NN + m0g + row) * CC + col] = p;
                }
            }
        }
    }
}

extern "C" void kernel_launch(void* const* d_in, const int* in_sizes, int n_in,
                              void* d_out, int out_size)
{
    const float* x    = (const float*)d_in[0];
    const float* H    = (const float*)d_in[1];
    const float* W    = (const float*)d_in[2];
    const float* bias = (const float*)d_in[3];
    float* out = (float*)d_out;

    const int sm01 = (2 * ASZ01 + 2 * BSZ) * 4;   // 69632 B
    const int sm2  = (2 * ASZ2  + 2 * BSZ) * 4;   // 71680 B
    cudaFuncSetAttribute(gemm_kernel<0>, cudaFuncAttributeMaxDynamicSharedMemorySize, sm01);
    cudaFuncSetAttribute(gemm_kernel<1>, cudaFuncAttributeMaxDynamicSharedMemorySize, sm01);
    cudaFuncSetAttribute(gemm_kernel<2>, cudaFuncAttributeMaxDynamicSharedMemorySize, sm2);

    gemm_kernel<0><<<dim3(EE / BM, BB, 2), 256, sm01>>>(x, H, W, bias, out);  // v2e split-K partials
    gemm_kernel<1><<<dim3(EE / BM, BB, 1), 256, sm01>>>(x, H, W, bias, out);  // combine + normalize + fc
    gemm_kernel<2><<<dim3(NN / BM, BB, 1), 256, sm2 >>>(x, H, W, bias, out);  // e2v + dv
}

// round 7
// speedup vs baseline: 3.0007x; 1.2780x over previous
#include <cuda_runtime.h>
#include <cuda_fp16.h>
#include <cstdint>

#define BB 8
#define NN 4096
#define EE 2048
#define CC 128

// ---------------- device scratch ----------------
__device__ float  g_e2 [2*BB*EE*CC];  // mode0 split-K partial edge features (fp32)
__device__ float  g_de2[2*BB*EE];     // mode0 split-K partial edge degrees
__device__ float  g_de [BB*EE];       // combined edge degrees
__device__ __half g_eh [BB*EE*CC];    // combined (unnormalized) edge feats, fp16
__device__ __half g_efh[BB*EE*CC];    // post-fc normalized edge feats, fp16
__device__ __half g_xh [BB*NN*CC];    // x in fp16
__device__ __half g_wh [CC*CC];       // W in fp16

__device__ __forceinline__ uint2 f4h(float4 v){
    __half2 a = __floats2half2_rn(v.x, v.y);
    __half2 b = __floats2half2_rn(v.z, v.w);
    uint2 r;
    r.x = *reinterpret_cast<uint32_t*>(&a);
    r.y = *reinterpret_cast<uint32_t*>(&b);
    return r;
}
__device__ __forceinline__ __half2 u2h(uint32_t u){ return *reinterpret_cast<__half2*>(&u); }

__device__ __forceinline__ void cpa16(uint32_t dst, const void* src){
    asm volatile("cp.async.cg.shared.global [%0], [%1], 16;\n" :: "r"(dst), "l"(src));
}
__device__ __forceinline__ void cp_commit(){ asm volatile("cp.async.commit_group;\n"); }

__device__ __forceinline__ void ldsm4(uint32_t* r, uint32_t a){
    asm volatile("ldmatrix.sync.aligned.m8n8.x4.shared.b16 {%0,%1,%2,%3}, [%4];"
                 : "=r"(r[0]),"=r"(r[1]),"=r"(r[2]),"=r"(r[3]) : "r"(a));
}
__device__ __forceinline__ void ldsm4t(uint32_t* r, uint32_t a){
    asm volatile("ldmatrix.sync.aligned.m8n8.x4.trans.shared.b16 {%0,%1,%2,%3}, [%4];"
                 : "=r"(r[0]),"=r"(r[1]),"=r"(r[2]),"=r"(r[3]) : "r"(a));
}
__device__ __forceinline__ void mma16(float* c, const uint32_t* a, const uint32_t* b){
    asm volatile(
        "mma.sync.aligned.m16n8k16.row.col.f32.f16.f16.f32 "
        "{%0,%1,%2,%3}, {%4,%5,%6,%7}, {%8,%9}, {%0,%1,%2,%3};"
        : "+f"(c[0]),"+f"(c[1]),"+f"(c[2]),"+f"(c[3])
        : "r"(a[0]),"r"(a[1]),"r"(a[2]),"r"(a[3]),"r"(b[0]),"r"(b[1]));
}

// ---------------- prep: fp16-convert x and W ----------------
__global__ void prep_kernel(const float* __restrict__ x, const float* __restrict__ W){
    const int NX4 = BB*NN*CC/4, NW4 = CC*CC/4;
    int i = blockIdx.x*256 + threadIdx.x;
    if (i < NX4){
        ((uint2*)g_xh)[i] = f4h(((const float4*)x)[i]);
    } else if (i - NX4 < NW4){
        ((uint2*)g_wh)[i-NX4] = f4h(((const float4*)W)[i-NX4]);
    }
}

// ---------------- combine split-K partials ----------------
__global__ void combine_kernel(){
    const int NF4 = BB*EE*CC/4, ND4 = BB*EE/4;
    int i = blockIdx.x*256 + threadIdx.x;
    if (i < NF4){
        float4 a = ((const float4*)g_e2)[i];
        float4 b = ((const float4*)g_e2)[i+NF4];
        a.x+=b.x; a.y+=b.y; a.z+=b.z; a.w+=b.w;
        ((uint2*)g_eh)[i] = f4h(a);
    } else if (i - NF4 < ND4){
        int j = i-NF4;
        float4 a = ((const float4*)g_de2)[j];
        float4 b = ((const float4*)g_de2)[j+ND4];
        a.x+=b.x; a.y+=b.y; a.z+=b.z; a.w+=b.w;
        ((float4*)g_de)[j] = a;
    }
}

// ---------------- fused fp16 GEMM kernels ----------------
// MODE 0: v2e split-K partials   A = H^T tile staged [k][m] (trans), B = g_xh
// MODE 1: fc                     A = g_eh [m][k] (non-trans),        B = g_wh
// MODE 2: e2v                    A = H tile [m][k] (non-trans),      B = g_efh
#define LDH  136   // halves; [k][*] tile row stride (17 x 16B, odd -> ldmatrix conflict-free)
#define LDMK 40    // halves; [m][k] tile row stride (5 x 16B, odd)

template<int MODE>
__global__ void __launch_bounds__(256,2)
hgemm_kernel(const float* __restrict__ H, const float* __restrict__ bias,
             float* __restrict__ out)
{
    constexpr int CHUNKS  = (MODE==0) ? NN/32/2 : (MODE==1 ? CC/32 : EE/32);
    constexpr int A_BYTES = (MODE==0) ? 32*LDH*2 : 128*LDMK*2;
    constexpr int B_BYTES = 32*LDH*2;
    constexpr int STB     = A_BYTES + B_BYTES;

    extern __shared__ char smraw[];
    __shared__ float deg_s[128];

    const int t=threadIdx.x, lane=t&31, wid=t>>5;
    const int b=blockIdx.y, m0g=blockIdx.x*128;
    const int split=(MODE==0)?blockIdx.z:0;
    const int kbase=(MODE==0)? split*CHUNKS*32 : 0;
    const int wm=wid>>1, wn=wid&1, gid=lane>>2, tig=lane&3;
    const int grp=lane>>3, gj=lane&7;

    const float* __restrict__ Hb = H + (size_t)b*NN*EE;
    const uint32_t smb = (uint32_t)__cvta_generic_to_shared(smraw);

    float acc[2][8][4];
#pragma unroll
    for (int i=0;i<2;i++)
#pragma unroll
        for (int j=0;j<8;j++)
#pragma unroll
            for (int r=0;r<4;r++) acc[i][j][r]=0.f;
    __half2 dg2[2][2];
    dg2[0][0]=dg2[0][1]=dg2[1][0]=dg2[1][1]=__floats2half2_rn(0.f,0.f);

    // ldmatrix per-lane address components
    const int a_k  = ((grp&2)?8:0) + gj;   // MODE0: k-offset (trans A)
    const int a_m0 = ((grp&1)?8:0);        // MODE0: m-offset
    const int a_r  = ((grp&1)?8:0) + gj;   // MODE1/2: m-offset (non-trans A)
    const int a_c  = ((grp&2)?8:0);        // MODE1/2: k-offset
    const int b_r  = ((grp&1)?8:0) + gj;   // B: k-offset (trans)
    const int b_c  = (grp>>1)*8;           // B: n-offset within pair

    auto stageB = [&](int kc, int buf){
        const int kg0 = kbase + kc*32;
        const uint32_t bB = smb + (uint32_t)(buf*STB + A_BYTES);
        const __half* src0 =
            (MODE==0) ? g_xh  + ((size_t)b*NN + kg0)*CC
          : (MODE==1) ? g_wh  + (size_t)kg0*CC
          :             g_efh + ((size_t)b*EE + kg0)*CC;
#pragma unroll
        for (int i=0;i<2;i++){
            const int idx = t + 256*i;
            const int k = idx>>4, n8 = (idx&15)*8;
            cpa16(bB + (uint32_t)((k*LDH + n8)*2), src0 + (size_t)k*CC + n8);
        }
    };
    auto stageA1 = [&](int kc, int buf){     // MODE1 A via cp.async
        const int kg0 = kc*32;
        const uint32_t aB = smb + (uint32_t)(buf*STB);
        const __half* src0 = g_eh + ((size_t)b*EE + m0g)*CC + kg0;
#pragma unroll
        for (int i=0;i<2;i++){
            const int idx = t + 256*i;
            const int m = idx>>2, k8 = (idx&3)*8;
            cpa16(aB + (uint32_t)((m*LDMK + k8)*2), src0 + (size_t)m*CC + k8);
        }
    };
    auto ldgA = [&](int kc, float4* r){      // MODE0/2: H fp32 prefetch
        const int kg0 = kbase + kc*32;
#pragma unroll
        for (int i=0;i<4;i++){
            const int idx = t + 256*i;
            if (MODE==0){
                const int k=idx>>5, m4=(idx&31)*4;
                r[i] = *(const float4*)(Hb + (size_t)(kg0+k)*EE + m0g + m4);
            } else {
                const int m=idx>>3, k4=(idx&7)*4;
                r[i] = *(const float4*)(Hb + (size_t)(m0g+m)*EE + kg0 + k4);
            }
        }
    };
    auto stsA = [&](const float4* r, int buf){
        const uint32_t aB = smb + (uint32_t)(buf*STB);
#pragma unroll
        for (int i=0;i<4;i++){
            const int idx = t + 256*i;
            uint2 h = f4h(r[i]);
            uint32_t d;
            if (MODE==0){ const int k=idx>>5, m4=(idx&31)*4; d = aB + (uint32_t)((k*LDH + m4)*2); }
            else        { const int m=idx>>3, k4=(idx&7)*4;  d = aB + (uint32_t)((m*LDMK + k4)*2); }
            asm volatile("st.shared.v2.b32 [%0], {%1,%2};" :: "r"(d), "r"(h.x), "r"(h.y));
        }
    };

    auto compute = [&](int buf){
        const uint32_t aB = smb + (uint32_t)(buf*STB);
        const uint32_t bB = aB + (uint32_t)A_BYTES;
#pragma unroll
        for (int s=0;s<2;s++){
            const int k0 = s*16;
            uint32_t a[2][4], bf[8][2];
#pragma unroll
            for (int mt=0;mt<2;mt++){
                if (MODE==0){
                    uint32_t ad = aB + (uint32_t)(((k0 + a_k)*LDH + wm*32 + mt*16 + a_m0)*2);
                    ldsm4t(a[mt], ad);
                } else {
                    uint32_t ad = aB + (uint32_t)(((wm*32 + mt*16 + a_r)*LDMK + k0 + a_c)*2);
                    ldsm4(a[mt], ad);
                }
            }
            if (MODE!=1 && wn==0){
#pragma unroll
                for (int mt=0;mt<2;mt++){
                    dg2[mt][0] = __hadd2(dg2[mt][0], __hadd2(u2h(a[mt][0]), u2h(a[mt][2])));
                    dg2[mt][1] = __hadd2(dg2[mt][1], __hadd2(u2h(a[mt][1]), u2h(a[mt][3])));
                }
            }
#pragma unroll
            for (int p=0;p<4;p++){
                uint32_t bd = bB + (uint32_t)(((k0 + b_r)*LDH + wn*64 + p*16 + b_c)*2);
                uint32_t r[4];
                ldsm4t(r, bd);
                bf[2*p  ][0]=r[0]; bf[2*p  ][1]=r[1];
                bf[2*p+1][0]=r[2]; bf[2*p+1][1]=r[3];
            }
#pragma unroll
            for (int mt=0;mt<2;mt++)
#pragma unroll
                for (int j=0;j<8;j++)
                    mma16(acc[mt][j], a[mt], bf[j]);
        }
    };

    // ---------------- mainloop ----------------
    if (MODE==1){
        stageA1(0,0); stageB(0,0); cp_commit();
        stageA1(1,1); stageB(1,1); cp_commit();
        for (int kc=0; kc<CHUNKS; kc++){
            asm volatile("cp.async.wait_group 1;" ::: "memory");
            __syncthreads();
            if (kc+2 < CHUNKS){ stageA1(kc+2,(kc+2)%3); stageB(kc+2,(kc+2)%3); }
            cp_commit();
            compute(kc%3);
        }
    } else {
        float4 rA[4];
        ldgA(0,rA); stsA(rA,0); stageB(0,0); cp_commit();
        ldgA(1,rA); stsA(rA,1); stageB(1,1); cp_commit();
        for (int kc=0; kc<CHUNKS; kc++){
            asm volatile("cp.async.wait_group 1;" ::: "memory");
            __syncthreads();
            const bool pre = (kc+2 < CHUNKS);
            if (pre){ ldgA(kc+2,rA); stageB(kc+2,(kc+2)%3); }
            cp_commit();
            compute(kc%3);
            if (pre) stsA(rA,(kc+2)%3);
        }
    }

    // ---------------- epilogue ----------------
    if (MODE==0){
#pragma unroll
        for (int mt=0;mt<2;mt++)
#pragma unroll
            for (int rh=0;rh<2;rh++){
                float2 f = __half22float2(dg2[mt][rh]);
                float v = f.x + f.y;
                v += __shfl_xor_sync(0xffffffffu, v, 1);
                v += __shfl_xor_sync(0xffffffffu, v, 2);
                if (wn==0 && tig==0)
                    g_de2[(size_t)split*BB*EE + (size_t)b*EE + m0g + wm*32+mt*16+rh*8+gid] = v;
            }
#pragma unroll
        for (int mt=0;mt<2;mt++)
#pragma unroll
            for (int rh=0;rh<2;rh++){
                const int row = wm*32+mt*16+rh*8+gid;
#pragma unroll
                for (int j=0;j<8;j++){
                    const int col = wn*64 + j*8 + tig*2;
                    *(float2*)&g_e2[(size_t)split*BB*EE*CC + ((size_t)b*EE+m0g+row)*CC + col]
                        = make_float2(acc[mt][j][rh*2], acc[mt][j][rh*2+1]);
                }
            }
        return;
    }

    if (MODE==2){
#pragma unroll
        for (int mt=0;mt<2;mt++)
#pragma unroll
            for (int rh=0;rh<2;rh++){
                float2 f = __half22float2(dg2[mt][rh]);
                float v = f.x + f.y;
                v += __shfl_xor_sync(0xffffffffu, v, 1);
                v += __shfl_xor_sync(0xffffffffu, v, 2);
                if (wn==0 && tig==0) deg_s[wm*32+mt*16+rh*8+gid] = v;
            }
        __syncthreads();
    } else {
        if (t < 128) deg_s[t] = g_de[(size_t)b*EE + m0g + t];
        __syncthreads();
    }

#pragma unroll
    for (int mt=0;mt<2;mt++)
#pragma unroll
        for (int rh=0;rh<2;rh++){
            const int row = wm*32+mt*16+rh*8+gid;
            const float d   = deg_s[row];
            const float inv = (d > 0.f) ? 1.f/d : 0.f;
#pragma unroll
            for (int j=0;j<8;j++){
                const int col = wn*64 + j*8 + tig*2;
                float v0 = acc[mt][j][rh*2  ]*inv;
                float v1 = acc[mt][j][rh*2+1]*inv;
                if (MODE==1){
                    v0 = (d>0.f) ? v0 + bias[col]   : 0.f;
                    v1 = (d>0.f) ? v1 + bias[col+1] : 0.f;
                    __half2 h = __floats2half2_rn(v0, v1);
                    *(uint32_t*)&g_efh[((size_t)b*EE+m0g+row)*CC + col] = *(uint32_t*)&h;
                } else {
                    *(float2*)&out[((size_t)b*NN+m0g+row)*CC + col] = make_float2(v0, v1);
                }
            }
        }
}

// ---------------- launcher ----------------
extern "C" void kernel_launch(void* const* d_in, const int* in_sizes, int n_in,
                              void* d_out, int out_size)
{
    const float* x    = (const float*)d_in[0];
    const float* H    = (const float*)d_in[1];
    const float* W    = (const float*)d_in[2];
    const float* bias = (const float*)d_in[3];
    float* out = (float*)d_out;

    const int sm0  = 3*(32*LDH*2  + 32*LDH*2);   // 52224 B
    const int sm12 = 3*(128*LDMK*2 + 32*LDH*2);  // 56832 B
    cudaFuncSetAttribute(hgemm_kernel<0>, cudaFuncAttributeMaxDynamicSharedMemorySize, sm0);
    cudaFuncSetAttribute(hgemm_kernel<1>, cudaFuncAttributeMaxDynamicSharedMemorySize, sm12);
    cudaFuncSetAttribute(hgemm_kernel<2>, cudaFuncAttributeMaxDynamicSharedMemorySize, sm12);

    const int prep_blk = (BB*NN*CC/4 + CC*CC/4 + 255)/256;
    const int comb_blk = (BB*EE*CC/4 + BB*EE/4 + 255)/256;

    prep_kernel    <<<prep_blk, 256>>>(x, W);
    hgemm_kernel<0><<<dim3(EE/128, BB, 2), 256, sm0 >>>(H, bias, out);
    combine_kernel <<<comb_blk, 256>>>();
    hgemm_kernel<1><<<dim3(EE/128, BB, 1), 256, sm12>>>(H, bias, out);
    hgemm_kernel<2><<<dim3(NN/128, BB, 1), 256, sm12>>>(H, bias, out);
}

// round 8
// speedup vs baseline: 3.3897x; 1.1296x over previous
#include <cuda_runtime.h>
#include <cuda_fp16.h>
#include <cstdint>

#define BB 8
#define NN 4096
#define EE 2048
#define CC 128

// ---------------- device scratch ----------------
__device__ __half g_hh [BB*NN*EE];    // H in fp16 (written by mode0, read by mode2)
__device__ float  g_de [BB*EE];       // edge degrees
__device__ __half g_eh [BB*EE*CC];    // unnormalized edge feats, fp16
__device__ __half g_efh[BB*EE*CC];    // post-fc normalized edge feats, fp16
__device__ __half g_xh [BB*NN*CC];    // x in fp16
__device__ __half g_wh [CC*CC];       // W in fp16

__device__ __forceinline__ uint2 f4h(float4 v){
    __half2 a = __floats2half2_rn(v.x, v.y);
    __half2 b = __floats2half2_rn(v.z, v.w);
    uint2 r;
    r.x = *reinterpret_cast<uint32_t*>(&a);
    r.y = *reinterpret_cast<uint32_t*>(&b);
    return r;
}
__device__ __forceinline__ __half2 u2h(uint32_t u){ return *reinterpret_cast<__half2*>(&u); }

__device__ __forceinline__ void cpa16(uint32_t dst, const void* src){
    asm volatile("cp.async.cg.shared.global [%0], [%1], 16;\n" :: "r"(dst), "l"(src));
}
__device__ __forceinline__ void cp_commit(){ asm volatile("cp.async.commit_group;\n"); }

__device__ __forceinline__ void ldsm4(uint32_t* r, uint32_t a){
    asm volatile("ldmatrix.sync.aligned.m8n8.x4.shared.b16 {%0,%1,%2,%3}, [%4];"
                 : "=r"(r[0]),"=r"(r[1]),"=r"(r[2]),"=r"(r[3]) : "r"(a));
}
__device__ __forceinline__ void ldsm4t(uint32_t* r, uint32_t a){
    asm volatile("ldmatrix.sync.aligned.m8n8.x4.trans.shared.b16 {%0,%1,%2,%3}, [%4];"
                 : "=r"(r[0]),"=r"(r[1]),"=r"(r[2]),"=r"(r[3]) : "r"(a));
}
__device__ __forceinline__ void mma16(float* c, const uint32_t* a, const uint32_t* b){
    asm volatile(
        "mma.sync.aligned.m16n8k16.row.col.f32.f16.f16.f32 "
        "{%0,%1,%2,%3}, {%4,%5,%6,%7}, {%8,%9}, {%0,%1,%2,%3};"
        : "+f"(c[0]),"+f"(c[1]),"+f"(c[2]),"+f"(c[3])
        : "r"(a[0]),"r"(a[1]),"r"(a[2]),"r"(a[3]),"r"(b[0]),"r"(b[1]));
}

// ---------------- prep: fp16-convert x and W ----------------
__global__ void prep_kernel(const float* __restrict__ x, const float* __restrict__ W){
    const int NX4 = BB*NN*CC/4, NW4 = CC*CC/4;
    int i = blockIdx.x*256 + threadIdx.x;
    if (i < NX4){
        ((uint2*)g_xh)[i] = f4h(((const float4*)x)[i]);
    } else if (i - NX4 < NW4){
        ((uint2*)g_wh)[i-NX4] = f4h(((const float4*)W)[i-NX4]);
    }
}

// ================= mode0: v2e (BM=64, full K=4096) + H transcode =================
// A = H^T tile staged [k][m] (trans ldmatrix), B = g_xh. Writes g_eh, g_de, g_hh.
#define LDH 136                  // halves; [k][*] row stride (17x16B, conflict-free)
#define A0_BYTES (32*LDH*2)      // 8704
#define B_BYTES  (32*LDH*2)      // 8704
#define STB0     (A0_BYTES + B_BYTES)

__global__ void __launch_bounds__(256,2)
v2e_kernel(const float* __restrict__ H)
{
    constexpr int CHUNKS = NN/32;   // 128
    extern __shared__ char smraw[];

    const int t=threadIdx.x, lane=t&31, wid=t>>5;
    const int b=blockIdx.y, m0g=blockIdx.x*64;
    const int wm=wid&1, wn=wid>>1;          // 2 row-groups x 4 col-groups
    const int gid=lane>>2, tig=lane&3;
    const int grp=lane>>3, gj=lane&7;

    const float* __restrict__ Hb = H + (size_t)b*NN*EE;
    const uint32_t smb = (uint32_t)__cvta_generic_to_shared(smraw);

    float acc[2][4][4];
#pragma unroll
    for (int i=0;i<2;i++)
#pragma unroll
        for (int j=0;j<4;j++)
#pragma unroll
            for (int r=0;r<4;r++) acc[i][j][r]=0.f;
    __half2 dg2[2][2];
    dg2[0][0]=dg2[0][1]=dg2[1][0]=dg2[1][1]=__floats2half2_rn(0.f,0.f);

    const int a_k  = ((grp&2)?8:0) + gj;
    const int a_m0 = ((grp&1)?8:0);
    const int b_r  = ((grp&1)?8:0) + gj;
    const int b_c  = (grp>>1)*8;

    auto ldgA = [&](int kc, float4* r){
        const int kg0 = kc*32;
#pragma unroll
        for (int i=0;i<2;i++){
            const int idx = t + 256*i;
            const int k = idx>>4, m4 = (idx&15)*4;
            r[i] = *(const float4*)(Hb + (size_t)(kg0+k)*EE + m0g + m4);
        }
    };
    auto stsA = [&](int kc, const float4* r, int buf){
        const int kg0 = kc*32;
        const uint32_t aB = smb + (uint32_t)(buf*STB0);
#pragma unroll
        for (int i=0;i<2;i++){
            const int idx = t + 256*i;
            const int k = idx>>4, m4 = (idx&15)*4;
            uint2 h = f4h(r[i]);
            asm volatile("st.shared.v2.b32 [%0], {%1,%2};"
                         :: "r"(aB + (uint32_t)((k*LDH + m4)*2)), "r"(h.x), "r"(h.y));
            *(uint2*)&g_hh[((size_t)b*NN + kg0 + k)*EE + m0g + m4] = h;  // H transcode
        }
    };
    auto stageB = [&](int kc, int buf){
        const int kg0 = kc*32;
        const uint32_t bB = smb + (uint32_t)(buf*STB0 + A0_BYTES);
        const __half* src0 = g_xh + ((size_t)b*NN + kg0)*CC;
#pragma unroll
        for (int i=0;i<2;i++){
            const int idx = t + 256*i;
            const int k = idx>>4, n8 = (idx&15)*8;
            cpa16(bB + (uint32_t)((k*LDH + n8)*2), src0 + (size_t)k*CC + n8);
        }
    };

    auto compute = [&](int buf){
        const uint32_t aB = smb + (uint32_t)(buf*STB0);
        const uint32_t bB = aB + (uint32_t)A0_BYTES;
#pragma unroll
        for (int s=0;s<2;s++){
            const int k0 = s*16;
            uint32_t a[2][4], bf[4][2];
#pragma unroll
            for (int mt=0;mt<2;mt++)
                ldsm4t(a[mt], aB + (uint32_t)(((k0 + a_k)*LDH + wm*32 + mt*16 + a_m0)*2));
            if (wn==0){
#pragma unroll
                for (int mt=0;mt<2;mt++){
                    dg2[mt][0] = __hadd2(dg2[mt][0], __hadd2(u2h(a[mt][0]), u2h(a[mt][2])));
                    dg2[mt][1] = __hadd2(dg2[mt][1], __hadd2(u2h(a[mt][1]), u2h(a[mt][3])));
                }
            }
#pragma unroll
            for (int p=0;p<2;p++){
                uint32_t r[4];
                ldsm4t(r, bB + (uint32_t)(((k0 + b_r)*LDH + wn*32 + p*16 + b_c)*2));
                bf[2*p  ][0]=r[0]; bf[2*p  ][1]=r[1];
                bf[2*p+1][0]=r[2]; bf[2*p+1][1]=r[3];
            }
#pragma unroll
            for (int mt=0;mt<2;mt++)
#pragma unroll
                for (int j=0;j<4;j++)
                    mma16(acc[mt][j], a[mt], bf[j]);
        }
    };

    float4 rA[2];
    ldgA(0,rA); stsA(0,rA,0); stageB(0,0); cp_commit();
    ldgA(1,rA); stsA(1,rA,1); stageB(1,1); cp_commit();
    for (int kc=0; kc<CHUNKS; kc++){
        asm volatile("cp.async.wait_group 1;" ::: "memory");
        __syncthreads();
        const bool pre = (kc+2 < CHUNKS);
        if (pre){ ldgA(kc+2,rA); stageB(kc+2,(kc+2)%3); }
        cp_commit();
        compute(kc%3);
        if (pre) stsA(kc+2,rA,(kc+2)%3);
    }

    // degrees (full, no split)
#pragma unroll
    for (int mt=0;mt<2;mt++)
#pragma unroll
        for (int rh=0;rh<2;rh++){
            float2 f = __half22float2(dg2[mt][rh]);
            float v = f.x + f.y;
            v += __shfl_xor_sync(0xffffffffu, v, 1);
            v += __shfl_xor_sync(0xffffffffu, v, 2);
            if (wn==0 && tig==0)
                g_de[(size_t)b*EE + m0g + wm*32+mt*16+rh*8+gid] = v;
        }
    // features -> fp16
#pragma unroll
    for (int mt=0;mt<2;mt++)
#pragma unroll
        for (int rh=0;rh<2;rh++){
            const int row = wm*32+mt*16+rh*8+gid;
#pragma unroll
            for (int j=0;j<4;j++){
                const int col = wn*32 + j*8 + tig*2;
                __half2 h = __floats2half2_rn(acc[mt][j][rh*2], acc[mt][j][rh*2+1]);
                *(uint32_t*)&g_eh[((size_t)b*EE+m0g+row)*CC + col] = *(uint32_t*)&h;
            }
        }
}

// ================= modes 1,2: pure cp.async fp16 GEMMs =================
// MODE 1: fc    A=g_eh [m][k], B=g_wh   -> g_efh (normalized + bias, masked)
// MODE 2: e2v   A=g_hh [m][k], B=g_efh  -> out (normalized by dv)
#define LDMK 40
#define A_BYTES12 (128*LDMK*2)   // 10240
#define STB12     (A_BYTES12 + B_BYTES)
#define NSTAGE 4

template<int MODE>
__global__ void __launch_bounds__(256,2)
hgemm_kernel(const float* __restrict__ bias, float* __restrict__ out)
{
    constexpr int CHUNKS = (MODE==1) ? CC/32 : EE/32;

    extern __shared__ char smraw[];
    __shared__ float deg_s[128];

    const int t=threadIdx.x, lane=t&31, wid=t>>5;
    const int b=blockIdx.y, m0g=blockIdx.x*128;
    const int wm=wid>>1, wn=wid&1, gid=lane>>2, tig=lane&3;
    const int grp=lane>>3, gj=lane&7;

    const uint32_t smb = (uint32_t)__cvta_generic_to_shared(smraw);

    float acc[2][8][4];
#pragma unroll
    for (int i=0;i<2;i++)
#pragma unroll
        for (int j=0;j<8;j++)
#pragma unroll
            for (int r=0;r<4;r++) acc[i][j][r]=0.f;
    __half2 dg2[2][2];
    dg2[0][0]=dg2[0][1]=dg2[1][0]=dg2[1][1]=__floats2half2_rn(0.f,0.f);

    const int a_r = ((grp&1)?8:0) + gj;
    const int a_c = ((grp&2)?8:0);
    const int b_r = ((grp&1)?8:0) + gj;
    const int b_c = (grp>>1)*8;

    auto stage = [&](int kc, int buf){
        const int kg0 = kc*32;
        const uint32_t aB = smb + (uint32_t)(buf*STB12);
        const uint32_t bB = aB + (uint32_t)A_BYTES12;
        const __half* asrc = (MODE==1)
            ? g_eh + ((size_t)b*EE + m0g)*CC + kg0
            : g_hh + ((size_t)b*NN + m0g)*EE + kg0;
        const size_t astr = (MODE==1) ? (size_t)CC : (size_t)EE;
#pragma unroll
        for (int i=0;i<2;i++){
            const int idx = t + 256*i;
            const int m = idx>>2, k8 = (idx&3)*8;
            cpa16(aB + (uint32_t)((m*LDMK + k8)*2), asrc + (size_t)m*astr + k8);
        }
        const __half* bsrc = (MODE==1)
            ? g_wh  + (size_t)kg0*CC
            : g_efh + ((size_t)b*EE + kg0)*CC;
#pragma unroll
        for (int i=0;i<2;i++){
            const int idx = t + 256*i;
            const int k = idx>>4, n8 = (idx&15)*8;
            cpa16(bB + (uint32_t)((k*LDH + n8)*2), bsrc + (size_t)k*CC + n8);
        }
    };

    auto compute = [&](int buf){
        const uint32_t aB = smb + (uint32_t)(buf*STB12);
        const uint32_t bB = aB + (uint32_t)A_BYTES12;
#pragma unroll
        for (int s=0;s<2;s++){
            const int k0 = s*16;
            uint32_t a[2][4], bf[8][2];
#pragma unroll
            for (int mt=0;mt<2;mt++)
                ldsm4(a[mt], aB + (uint32_t)(((wm*32 + mt*16 + a_r)*LDMK + k0 + a_c)*2));
            if (MODE==2 && wn==0){
#pragma unroll
                for (int mt=0;mt<2;mt++){
                    dg2[mt][0] = __hadd2(dg2[mt][0], __hadd2(u2h(a[mt][0]), u2h(a[mt][2])));
                    dg2[mt][1] = __hadd2(dg2[mt][1], __hadd2(u2h(a[mt][1]), u2h(a[mt][3])));
                }
            }
#pragma unroll
            for (int p=0;p<4;p++){
                uint32_t r[4];
                ldsm4t(r, bB + (uint32_t)(((k0 + b_r)*LDH + wn*64 + p*16 + b_c)*2));
                bf[2*p  ][0]=r[0]; bf[2*p  ][1]=r[1];
                bf[2*p+1][0]=r[2]; bf[2*p+1][1]=r[3];
            }
#pragma unroll
            for (int mt=0;mt<2;mt++)
#pragma unroll
                for (int j=0;j<8;j++)
                    mma16(acc[mt][j], a[mt], bf[j]);
        }
    };

    // 4-stage pipeline
#pragma unroll
    for (int s=0; s<NSTAGE-1; s++){
        if (s < CHUNKS) stage(s, s);
        cp_commit();
    }
    for (int kc=0; kc<CHUNKS; kc++){
        asm volatile("cp.async.wait_group %0;" :: "n"(NSTAGE-2) : "memory");
        __syncthreads();
        if (kc+NSTAGE-1 < CHUNKS) stage(kc+NSTAGE-1, (kc+NSTAGE-1)%NSTAGE);
        cp_commit();
        compute(kc%NSTAGE);
    }

    if (MODE==2){
#pragma unroll
        for (int mt=0;mt<2;mt++)
#pragma unroll
            for (int rh=0;rh<2;rh++){
                float2 f = __half22float2(dg2[mt][rh]);
                float v = f.x + f.y;
                v += __shfl_xor_sync(0xffffffffu, v, 1);
                v += __shfl_xor_sync(0xffffffffu, v, 2);
                if (wn==0 && tig==0) deg_s[wm*32+mt*16+rh*8+gid] = v;
            }
        __syncthreads();
    } else {
        if (t < 128) deg_s[t] = g_de[(size_t)b*EE + m0g + t];
        __syncthreads();
    }

#pragma unroll
    for (int mt=0;mt<2;mt++)
#pragma unroll
        for (int rh=0;rh<2;rh++){
            const int row = wm*32+mt*16+rh*8+gid;
            const float d   = deg_s[row];
            const float inv = (d > 0.f) ? 1.f/d : 0.f;
#pragma unroll
            for (int j=0;j<8;j++){
                const int col = wn*64 + j*8 + tig*2;
                float v0 = acc[mt][j][rh*2  ]*inv;
                float v1 = acc[mt][j][rh*2+1]*inv;
                if (MODE==1){
                    v0 = (d>0.f) ? v0 + bias[col]   : 0.f;
                    v1 = (d>0.f) ? v1 + bias[col+1] : 0.f;
                    __half2 h = __floats2half2_rn(v0, v1);
                    *(uint32_t*)&g_efh[((size_t)b*EE+m0g+row)*CC + col] = *(uint32_t*)&h;
                } else {
                    *(float2*)&out[((size_t)b*NN+m0g+row)*CC + col] = make_float2(v0, v1);
                }
            }
        }
}

// ---------------- launcher ----------------
extern "C" void kernel_launch(void* const* d_in, const int* in_sizes, int n_in,
                              void* d_out, int out_size)
{
    const float* x    = (const float*)d_in[0];
    const float* H    = (const float*)d_in[1];
    const float* W    = (const float*)d_in[2];
    const float* bias = (const float*)d_in[3];
    float* out = (float*)d_out;

    const int sm0  = 3*STB0;        // 52224 B
    const int sm12 = NSTAGE*STB12;  // 75776 B
    cudaFuncSetAttribute(v2e_kernel,      cudaFuncAttributeMaxDynamicSharedMemorySize, sm0);
    cudaFuncSetAttribute(hgemm_kernel<1>, cudaFuncAttributeMaxDynamicSharedMemorySize, sm12);
    cudaFuncSetAttribute(hgemm_kernel<2>, cudaFuncAttributeMaxDynamicSharedMemorySize, sm12);

    const int prep_blk = (BB*NN*CC/4 + CC*CC/4 + 255)/256;

    prep_kernel    <<<prep_blk, 256>>>(x, W);
    v2e_kernel     <<<dim3(EE/64,  BB), 256, sm0 >>>(H);
    hgemm_kernel<1><<<dim3(EE/128, BB), 256, sm12>>>(bias, out);
    hgemm_kernel<2><<<dim3(NN/128, BB), 256, sm12>>>(bias, out);
}